// round 11
// baseline (speedup 1.0000x reference)
#include <cuda_runtime.h>
#include <cuda_bf16.h>
#include <cstdint>

#define BQ   2048
#define DD   128
#define MM   256
#define NK   32768
#define EST_CONST 0.0048957583f   // sqrt(pi/2)/256

#define TILE_N 128
#define NCB    (NK / TILE_N)      // 256 column blocks
#define KMAIN  384                // [Qhi|Qlo|Qhi] x [KDhi|KDhi|KDlo]
#define NRB    (BQ / 128)         // 16 row blocks
#define GTILES (NRB * NCB)        // 4096
#define LAG    296
#define GRID_X (GTILES + LAG)     // 4392

// ---------------- device scratch ----------------
__device__ __align__(16) __nv_bfloat16 g_Kb[NK * MM];      // keys bf16 exact
__device__ __align__(16) __nv_bfloat16 g_Sd[DD * 512];     // S^T hi|lo  [d][512]
__device__ __align__(16) __nv_bfloat16 g_Ap[BQ * KMAIN];   // [Qhi|Qlo|Qhi]
__device__ __align__(16) __nv_bfloat16 g_Bp[NK * KMAIN];   // [KDhi|KDhi|KDlo]
__device__ float g_scl[NK];
__device__ float g_pmax[BQ * NCB];
__device__ float g_psum[BQ * NCB];
__device__ float g_rowm[BQ];
__device__ float g_rowinv[BQ];
__device__ int   g_cnt[NRB];
__device__ unsigned g_flag[NRB];

__device__ __forceinline__ uint32_t smem_u32(const void* p) {
    uint32_t a;
    asm("{ .reg .u64 t; cvta.to.shared.u64 t, %1; cvt.u32.u64 %0, t; }" : "=r"(a) : "l"(p));
    return a;
}
#define CP16(dst, src) asm volatile("cp.async.cg.shared.global [%0], [%1], 16;" :: "r"(dst), "l"(src))
#define CP_COMMIT()    asm volatile("cp.async.commit_group;" ::: "memory")

// ---------------- kernel i: reset control state ----------------
__global__ void init_kernel() {
    if (threadIdx.x < NRB) { g_cnt[threadIdx.x] = 0; g_flag[threadIdx.x] = 0u; }
}

// ---------------- kernel 0: keys -> bf16 (exact), scales --------------------
__global__ __launch_bounds__(256) void convert_keys_kernel(const float* __restrict__ keys,
                                                           const float* __restrict__ norms) {
    int i = blockIdx.x * blockDim.x + threadIdx.x;   // over float4
    float4 v = ((const float4*)keys)[i];
    __nv_bfloat162* o = (__nv_bfloat162*)g_Kb;
    o[i * 2]     = __nv_bfloat162(__float2bfloat16(v.x), __float2bfloat16(v.y));
    o[i * 2 + 1] = __nv_bfloat162(__float2bfloat16(v.z), __float2bfloat16(v.w));
    if (i < NK) g_scl[i] = EST_CONST * norms[i];
}

// ---------------- kernel 0b: S -> transposed hi/lo --------------------------
__global__ __launch_bounds__(256) void prep_S_kernel(const float* __restrict__ S) {
    int idx = blockIdx.x * blockDim.x + threadIdx.x;   // 32768 elems
    int m = idx >> 7, d = idx & 127;
    float v = S[m * DD + d];
    __nv_bfloat16 hi = __float2bfloat16(v);
    float lo = v - __bfloat162float(hi);
    g_Sd[d * 512 + m]       = hi;
    g_Sd[d * 512 + 256 + m] = __float2bfloat16(lo);
}

// ---------------- kernel 0c: Q -> [Qhi|Qlo|Qhi] -----------------------------
__global__ __launch_bounds__(256) void prep_A_kernel(const float* __restrict__ q) {
    int idx = blockIdx.x * blockDim.x + threadIdx.x;   // 2048*128
    int b = idx >> 7, d = idx & 127;
    float v = q[idx];
    __nv_bfloat16 hi = __float2bfloat16(v);
    float lo = v - __bfloat162float(hi);
    g_Ap[b * KMAIN + d]       = hi;
    g_Ap[b * KMAIN + 128 + d] = __float2bfloat16(lo);
    g_Ap[b * KMAIN + 256 + d] = hi;
}

// ---------------- shared GEMM machinery ----------------
#define RSE 72                          // smem row elems (144 B)
#define TBYTES (128 * RSE * 2)          // 18432 per operand tile
#define STAGE_BYTES (2 * TBYTES)        // 36864
#define SMEM_BYTES  (3 * STAGE_BYTES)   // 110592

extern __shared__ char dsm[];

#define HMMA(acc, a, b0, b1) \
    asm volatile("mma.sync.aligned.m16n8k16.row.col.f32.bf16.bf16.f32 " \
                 "{%0,%1,%2,%3}, {%4,%5,%6,%7}, {%8,%9}, {%0,%1,%2,%3};" \
                 : "+f"((acc)[0]), "+f"((acc)[1]), "+f"((acc)[2]), "+f"((acc)[3]) \
                 : "r"((a)[0]), "r"((a)[1]), "r"((a)[2]), "r"((a)[3]), "r"(b0), "r"(b1))

#define LDSM4(f, addr) \
    asm volatile("ldmatrix.sync.aligned.m8n8.x4.shared.b16 {%0,%1,%2,%3}, [%4];" \
                 : "=r"((f)[0]), "=r"((f)[1]), "=r"((f)[2]), "=r"((f)[3]) : "r"(addr))

__device__ __forceinline__ void compute_chunk(uint32_t base, int wm, int wn,
                                              int lrow, int lcolo, float acc[2][8][4]) {
    uint32_t bbase = base + TBYTES;
#pragma unroll
    for (int kk = 0; kk < 64; kk += 16) {
        uint32_t a[2][4];
#pragma unroll
        for (int mf = 0; mf < 2; mf++)
            LDSM4(a[mf], base + (uint32_t)((wm * 32 + mf * 16 + lrow) * (RSE * 2)
                                           + (kk + lcolo) * 2));
        uint32_t b[8][2];
#pragma unroll
        for (int nq = 0; nq < 4; nq++) {
            uint32_t f[4];
            LDSM4(f, bbase + (uint32_t)((wn * 64 + nq * 16 + lrow) * (RSE * 2)
                                        + (kk + lcolo) * 2));
            b[nq * 2][0] = f[0];     b[nq * 2][1] = f[2];
            b[nq * 2 + 1][0] = f[1]; b[nq * 2 + 1][1] = f[3];
        }
#pragma unroll
        for (int mf = 0; mf < 2; mf++)
#pragma unroll
            for (int nf = 0; nf < 8; nf++)
                HMMA(acc[mf][nf], a[mf], b[nf][0], b[nf][1]);
    }
}

__device__ __forceinline__ void load_tiles(uint32_t base, int tid,
                                           const __nv_bfloat16* __restrict__ Ag, int astr,
                                           const __nv_bfloat16* __restrict__ Bg, int bstr) {
#pragma unroll
    for (int i = 0; i < 4; i++) {
        int u = tid + i * 256;
        int r = u >> 3, c = (u & 7) * 8;
        uint32_t off = (uint32_t)(r * (RSE * 2) + c * 2);
        CP16(base + off,          &Ag[(size_t)r * astr + c]);
        CP16(base + TBYTES + off, &Bg[(size_t)r * bstr + c]);
    }
}

// ---------------- kernel 1: KD = keys*S (hi/lo), pack B' --------------------
// 64-key tiles; 2-stage pipeline, 3 CTAs/SM for latency hiding.
#define KD_ABYTES 9216
#define KD_STAGE  27648
#define KD_SMEM   (2 * KD_STAGE)

__device__ __forceinline__ void kd_load(uint32_t base, int tid,
                                        const __nv_bfloat16* __restrict__ Ag,
                                        const __nv_bfloat16* __restrict__ Bg) {
#pragma unroll
    for (int i = 0; i < 2; i++) {         // A: 64 rows x 128B
        int u = tid + i * 256;
        int r = u >> 3, c = (u & 7) * 8;
        CP16(base + (uint32_t)(r * (RSE * 2) + c * 2), &Ag[(size_t)r * MM + c]);
    }
#pragma unroll
    for (int i = 0; i < 4; i++) {         // B: 128 rows x 128B
        int u = tid + i * 256;
        int r = u >> 3, c = (u & 7) * 8;
        CP16(base + KD_ABYTES + (uint32_t)(r * (RSE * 2) + c * 2), &Bg[(size_t)r * 512 + c]);
    }
}

__global__ __launch_bounds__(256, 3) void kd_kernel() {
    uint32_t sb = smem_u32(dsm);
    int tid = threadIdx.x, warp = tid >> 5, lane = tid & 31;
    int wm = warp >> 1, wn = warp & 1;
    int n0 = blockIdx.x * 64;

    float acc[8][4];
#pragma unroll
    for (int j = 0; j < 8; j++)
#pragma unroll
        for (int k = 0; k < 4; k++) acc[j][k] = 0.f;

    int lrow  = (lane & 7) + (lane & 8);
    int lcolo = (lane >> 4) << 3;

#define KD_LOAD(st, c) kd_load(sb + (st) * KD_STAGE, tid, \
        &g_Kb[(size_t)n0 * MM + (((c) * 64) & 255)], &g_Sd[(c) * 64])

    KD_LOAD(0, 0); CP_COMMIT();
    KD_LOAD(1, 1); CP_COMMIT();
#pragma unroll 1
    for (int c = 0; c < 8; c++) {
        if (c < 7) asm volatile("cp.async.wait_group 1;" ::: "memory");
        else       asm volatile("cp.async.wait_group 0;" ::: "memory");
        __syncthreads();
        uint32_t base = sb + (c & 1) * KD_STAGE;
        uint32_t bbase = base + KD_ABYTES;
#pragma unroll
        for (int kk = 0; kk < 64; kk += 16) {
            uint32_t a[4];
            LDSM4(a, base + (uint32_t)((wm * 16 + lrow) * (RSE * 2) + (kk + lcolo) * 2));
            uint32_t b[8][2];
#pragma unroll
            for (int nq = 0; nq < 4; nq++) {
                uint32_t f[4];
                LDSM4(f, bbase + (uint32_t)((wn * 64 + nq * 16 + lrow) * (RSE * 2)
                                            + (kk + lcolo) * 2));
                b[nq * 2][0] = f[0];     b[nq * 2][1] = f[2];
                b[nq * 2 + 1][0] = f[1]; b[nq * 2 + 1][1] = f[3];
            }
#pragma unroll
            for (int nf = 0; nf < 8; nf++)
                HMMA(acc[nf], a, b[nf][0], b[nf][1]);
        }
        if (c + 2 < 8) {
            __syncthreads();              // all readers done with stage c&1
            KD_LOAD(c & 1, c + 2); CP_COMMIT();
        }
    }

    int q = lane & 3, rq = lane >> 2;
#pragma unroll
    for (int nf = 0; nf < 8; nf++) {
        int col = wn * 64 + nf * 8 + q * 2;
#pragma unroll
        for (int h = 0; h < 2; h++) {
            int r = wm * 16 + h * 8 + rq;
            float v0 = acc[nf][h * 2 + 0];
            float v1 = acc[nf][h * 2 + 1];
            __nv_bfloat16 h0 = __float2bfloat16(v0);
            __nv_bfloat16 h1 = __float2bfloat16(v1);
            __nv_bfloat162 hp(h0, h1);
            __nv_bfloat162 lp(__float2bfloat16(v0 - __bfloat162float(h0)),
                              __float2bfloat16(v1 - __bfloat162float(h1)));
            size_t rb = (size_t)(n0 + r) * KMAIN;
            *(__nv_bfloat162*)&g_Bp[rb + col]       = hp;
            *(__nv_bfloat162*)&g_Bp[rb + 128 + col] = hp;
            *(__nv_bfloat162*)&g_Bp[rb + 256 + col] = lp;
        }
    }
}

// ---------------- kernel 2: fused GEMM + softmax (flags, L2-resident) -------
__global__ __launch_bounds__(256, 2) void gemm_kernel(float* __restrict__ out) {
    uint32_t sb = smem_u32(dsm);
    int tid = threadIdx.x, warp = tid >> 5, lane = tid & 31;
    int wm = warp >> 1, wn = warp & 1;
    int t = blockIdx.x;

    __shared__ float sclS[TILE_N];
    __shared__ float redm[128][2];
    __shared__ float reds[128][2];
    __shared__ int sTicket;

    if (t < GTILES) {
        int rb = t >> 8, cb = t & 255;
        int row0 = rb * 128, col0 = cb * TILE_N;
        if (tid < TILE_N) sclS[tid] = g_scl[col0 + tid];

        float acc[2][8][4];
#pragma unroll
        for (int i = 0; i < 2; i++)
#pragma unroll
            for (int j = 0; j < 8; j++)
#pragma unroll
                for (int k = 0; k < 4; k++) acc[i][j][k] = 0.f;

        int lrow  = (lane & 7) + (lane & 8);
        int lcolo = (lane >> 4) << 3;

#define MG_LOAD(st, c) load_tiles(sb + (st) * STAGE_BYTES, tid, \
        &g_Ap[(size_t)row0 * KMAIN + (c) * 64], KMAIN, \
        &g_Bp[(size_t)col0 * KMAIN + (c) * 64], KMAIN)

        MG_LOAD(0, 0); CP_COMMIT();
        MG_LOAD(1, 1); CP_COMMIT();
#pragma unroll 1
        for (int c = 0; c < 6; c++) {
            if (c < 5) asm volatile("cp.async.wait_group 1;" ::: "memory");
            else       asm volatile("cp.async.wait_group 0;" ::: "memory");
            __syncthreads();
            if (c + 2 < 6) { MG_LOAD((c + 2) % 3, c + 2); CP_COMMIT(); }
            compute_chunk(sb + (c % 3) * STAGE_BYTES, wm, wn, lrow, lcolo, acc);
        }
        __syncthreads();

        // epilogue: scale + stats + staged coalesced store
        float* stage = (float*)dsm;            // [128][132] fp32
        int q = lane & 3, rq = lane >> 2;

        float rmax[2][2];
#pragma unroll
        for (int mf = 0; mf < 2; mf++)
#pragma unroll
            for (int h = 0; h < 2; h++) rmax[mf][h] = -1e30f;

#pragma unroll
        for (int mf = 0; mf < 2; mf++)
#pragma unroll
            for (int nf = 0; nf < 8; nf++) {
                int c = wn * 64 + nf * 8 + q * 2;
                float s0 = sclS[c], s1 = sclS[c + 1];
#pragma unroll
                for (int h = 0; h < 2; h++) {
                    float v0 = acc[mf][nf][h * 2 + 0] * s0;
                    float v1 = acc[mf][nf][h * 2 + 1] * s1;
                    acc[mf][nf][h * 2 + 0] = v0;
                    acc[mf][nf][h * 2 + 1] = v1;
                    rmax[mf][h] = fmaxf(rmax[mf][h], fmaxf(v0, v1));
                    int r = wm * 32 + mf * 16 + h * 8 + rq;
                    stage[r * 132 + c]     = v0;
                    stage[r * 132 + c + 1] = v1;
                }
            }

#pragma unroll
        for (int mf = 0; mf < 2; mf++)
#pragma unroll
            for (int h = 0; h < 2; h++) {
                float m = rmax[mf][h];
                m = fmaxf(m, __shfl_xor_sync(0xffffffff, m, 1));
                m = fmaxf(m, __shfl_xor_sync(0xffffffff, m, 2));
                if (q == 0) redm[wm * 32 + mf * 16 + h * 8 + rq][wn] = m;
            }
        __syncthreads();

#pragma unroll
        for (int mf = 0; mf < 2; mf++)
#pragma unroll
            for (int h = 0; h < 2; h++) {
                int r = wm * 32 + mf * 16 + h * 8 + rq;
                float m = fmaxf(redm[r][0], redm[r][1]);
                float s = 0.f;
#pragma unroll
                for (int nf = 0; nf < 8; nf++) {
                    s += __expf(acc[mf][nf][h * 2 + 0] - m);
                    s += __expf(acc[mf][nf][h * 2 + 1] - m);
                }
                s += __shfl_xor_sync(0xffffffff, s, 1);
                s += __shfl_xor_sync(0xffffffff, s, 2);
                if (q == 0) reds[r][wn] = s;
            }
        __syncthreads();

        if (tid < 128) {
            float m = fmaxf(redm[tid][0], redm[tid][1]);
            float s = reds[tid][0] + reds[tid][1];
            g_pmax[(size_t)(row0 + tid) * NCB + cb] = m;
            g_psum[(size_t)(row0 + tid) * NCB + cb] = s;
        }

#pragma unroll
        for (int rr = 0; rr < 4; rr++) {
            int r = rr * 32 + warp * 4 + (lane >> 3);
#pragma unroll
            for (int k = 0; k < 4; k++) {
                int col = (lane & 7) * 4 + k * 32;
                float4 v = *(const float4*)&stage[r * 132 + col];
                *(float4*)&out[(size_t)(row0 + r) * NK + col0 + col] = v;
            }
        }

        // release: partials + raw tile visible, then count
        __threadfence();
        if (tid == 0) sTicket = atomicAdd(&g_cnt[rb], 1);
        __syncthreads();

        if (sTicket == NCB - 1) {
            // last CTA of this row block: reduce 256 partials for 128 rows
            __threadfence();
            int r = tid >> 1, h = tid & 1;
            const float4* pm4 = (const float4*)&g_pmax[(size_t)(row0 + r) * NCB + h * 128];
            const float4* ps4 = (const float4*)&g_psum[(size_t)(row0 + r) * NCB + h * 128];
            float M = -1e30f;
#pragma unroll 4
            for (int i = 0; i < 32; i++) {
                float4 a = pm4[i];
                M = fmaxf(M, fmaxf(fmaxf(a.x, a.y), fmaxf(a.z, a.w)));
            }
            M = fmaxf(M, __shfl_xor_sync(0xffffffff, M, 1));
            float s = 0.f;
#pragma unroll 4
            for (int i = 0; i < 32; i++) {
                float4 a = pm4[i], b = ps4[i];
                s += b.x * __expf(a.x - M) + b.y * __expf(a.y - M)
                   + b.z * __expf(a.z - M) + b.w * __expf(a.w - M);
            }
            s += __shfl_xor_sync(0xffffffff, s, 1);
            if (h == 0) {
                g_rowm[row0 + r]   = M;
                g_rowinv[row0 + r] = 1.f / s;
            }
            __threadfence();
            __syncthreads();
            if (tid == 0) atomicExch(&g_flag[rb], 1u);
        }
    }

    // ---------------- deferred finalize of tile t - LAG ----------------
    int ft = t - LAG;
    if (ft >= 0) {
        int frb = ft >> 8, fcb = ft & 255;
        int frow0 = frb * 128, fcol0 = fcb * TILE_N;
        if (tid == 0) {
            unsigned v;
            do {
                asm volatile("ld.acquire.gpu.u32 %0, [%1];" : "=r"(v) : "l"(&g_flag[frb]) : "memory");
                if (!v) __nanosleep(128);
            } while (!v);
        }
        __syncthreads();
        int r2 = tid >> 1, hh = tid & 1;
        float m   = g_rowm[frow0 + r2];
        float inv = g_rowinv[frow0 + r2];
        float4* p = (float4*)&out[(size_t)(frow0 + r2) * NK + fcol0 + hh * 64];
#pragma unroll 4
        for (int k = 0; k < 16; k++) {
            float4 v = p[k];
            v.x = __expf(v.x - m) * inv;
            v.y = __expf(v.y - m) * inv;
            v.z = __expf(v.z - m) * inv;
            v.w = __expf(v.w - m) * inv;
            p[k] = v;
        }
    }
}

// ---------------- launcher ----------------
extern "C" void kernel_launch(void* const* d_in, const int* in_sizes, int n_in,
                              void* d_out, int out_size) {
    const float* query  = (const float*)d_in[0];
    const float* keys   = (const float*)d_in[1];
    const float* norms  = (const float*)d_in[2];
    const float* sketch = (const float*)d_in[3];
    float* out = (float*)d_out;

    cudaFuncSetAttribute(kd_kernel,   cudaFuncAttributeMaxDynamicSharedMemorySize, KD_SMEM);
    cudaFuncSetAttribute(gemm_kernel, cudaFuncAttributeMaxDynamicSharedMemorySize, SMEM_BYTES);

    init_kernel<<<1, 32>>>();
    convert_keys_kernel<<<NK * MM / 1024, 256>>>(keys, norms);
    prep_S_kernel<<<MM * DD / 256, 256>>>(sketch);
    prep_A_kernel<<<BQ * DD / 256, 256>>>(query);
    kd_kernel<<<NK / 64, 256, KD_SMEM>>>();
    gemm_kernel<<<GRID_X, 256, SMEM_BYTES>>>(out);
}

// round 12
// speedup vs baseline: 1.4587x; 1.4587x over previous
#include <cuda_runtime.h>
#include <cuda_bf16.h>
#include <cstdint>

#define BQ   2048
#define DD   128
#define MM   256
#define NK   32768
#define EST_CONST 0.0048957583f   // sqrt(pi/2)/256

#define TILE_N 128
#define NCB    (NK / TILE_N)      // 256 column blocks
#define KMAIN  384                // [Qhi|Qlo|Qhi] x [KDhi|KDhi|KDlo]
#define NRB    (BQ / 128)         // 16 row blocks
#define NQUART 4
#define RB_PER_Q (NRB / NQUART)   // 4 row blocks per quarter (512 rows)

// ---------------- device scratch ----------------
__device__ __align__(16) __nv_bfloat16 g_Kb[NK * MM];      // keys bf16 exact
__device__ __align__(16) __nv_bfloat16 g_Sd[DD * 512];     // S^T hi|lo  [d][512]
__device__ __align__(16) __nv_bfloat16 g_Ap[BQ * KMAIN];   // [Qhi|Qlo|Qhi]
__device__ __align__(16) __nv_bfloat16 g_Bp[NK * KMAIN];   // [KDhi|KDhi|KDlo]
__device__ float g_scl[NK];
__device__ float g_pmax[BQ * NCB];
__device__ float g_psum[BQ * NCB];
__device__ float g_rowm[BQ];
__device__ float g_rowinv[BQ];

__device__ __forceinline__ uint32_t smem_u32(const void* p) {
    uint32_t a;
    asm("{ .reg .u64 t; cvta.to.shared.u64 t, %1; cvt.u32.u64 %0, t; }" : "=r"(a) : "l"(p));
    return a;
}
#define CP16(dst, src) asm volatile("cp.async.cg.shared.global [%0], [%1], 16;" :: "r"(dst), "l"(src))
#define CP_COMMIT()    asm volatile("cp.async.commit_group;" ::: "memory")

// ---------------- kernel 0: keys -> bf16 (exact), scales --------------------
__global__ __launch_bounds__(256) void convert_keys_kernel(const float* __restrict__ keys,
                                                           const float* __restrict__ norms) {
    int i = blockIdx.x * blockDim.x + threadIdx.x;   // over float4
    float4 v = ((const float4*)keys)[i];
    __nv_bfloat162* o = (__nv_bfloat162*)g_Kb;
    o[i * 2]     = __nv_bfloat162(__float2bfloat16(v.x), __float2bfloat16(v.y));
    o[i * 2 + 1] = __nv_bfloat162(__float2bfloat16(v.z), __float2bfloat16(v.w));
    if (i < NK) g_scl[i] = EST_CONST * norms[i];
}

// ---------------- kernel 0b: S -> transposed hi/lo --------------------------
__global__ __launch_bounds__(256) void prep_S_kernel(const float* __restrict__ S) {
    int idx = blockIdx.x * blockDim.x + threadIdx.x;   // 32768 elems
    int m = idx >> 7, d = idx & 127;
    float v = S[m * DD + d];
    __nv_bfloat16 hi = __float2bfloat16(v);
    float lo = v - __bfloat162float(hi);
    g_Sd[d * 512 + m]       = hi;
    g_Sd[d * 512 + 256 + m] = __float2bfloat16(lo);
}

// ---------------- kernel 0c: Q -> [Qhi|Qlo|Qhi] -----------------------------
__global__ __launch_bounds__(256) void prep_A_kernel(const float* __restrict__ q) {
    int idx = blockIdx.x * blockDim.x + threadIdx.x;   // 2048*128
    int b = idx >> 7, d = idx & 127;
    float v = q[idx];
    __nv_bfloat16 hi = __float2bfloat16(v);
    float lo = v - __bfloat162float(hi);
    g_Ap[b * KMAIN + d]       = hi;
    g_Ap[b * KMAIN + 128 + d] = __float2bfloat16(lo);
    g_Ap[b * KMAIN + 256 + d] = hi;
}

// ---------------- shared GEMM machinery ----------------
#define RSE 72                          // smem row elems (144 B)
#define TBYTES (128 * RSE * 2)          // 18432 per operand tile
#define STAGE_BYTES (2 * TBYTES)        // 36864
#define SMEM_BYTES  (3 * STAGE_BYTES)   // 110592

extern __shared__ char dsm[];

#define HMMA(acc, a, b0, b1) \
    asm volatile("mma.sync.aligned.m16n8k16.row.col.f32.bf16.bf16.f32 " \
                 "{%0,%1,%2,%3}, {%4,%5,%6,%7}, {%8,%9}, {%0,%1,%2,%3};" \
                 : "+f"((acc)[0]), "+f"((acc)[1]), "+f"((acc)[2]), "+f"((acc)[3]) \
                 : "r"((a)[0]), "r"((a)[1]), "r"((a)[2]), "r"((a)[3]), "r"(b0), "r"(b1))

#define LDSM4(f, addr) \
    asm volatile("ldmatrix.sync.aligned.m8n8.x4.shared.b16 {%0,%1,%2,%3}, [%4];" \
                 : "=r"((f)[0]), "=r"((f)[1]), "=r"((f)[2]), "=r"((f)[3]) : "r"(addr))

__device__ __forceinline__ void compute_chunk(uint32_t base, int wm, int wn,
                                              int lrow, int lcolo, float acc[2][8][4]) {
    uint32_t bbase = base + TBYTES;
#pragma unroll
    for (int kk = 0; kk < 64; kk += 16) {
        uint32_t a[2][4];
#pragma unroll
        for (int mf = 0; mf < 2; mf++)
            LDSM4(a[mf], base + (uint32_t)((wm * 32 + mf * 16 + lrow) * (RSE * 2)
                                           + (kk + lcolo) * 2));
        uint32_t b[8][2];
#pragma unroll
        for (int nq = 0; nq < 4; nq++) {
            uint32_t f[4];
            LDSM4(f, bbase + (uint32_t)((wn * 64 + nq * 16 + lrow) * (RSE * 2)
                                        + (kk + lcolo) * 2));
            b[nq * 2][0] = f[0];     b[nq * 2][1] = f[2];
            b[nq * 2 + 1][0] = f[1]; b[nq * 2 + 1][1] = f[3];
        }
#pragma unroll
        for (int mf = 0; mf < 2; mf++)
#pragma unroll
            for (int nf = 0; nf < 8; nf++)
                HMMA(acc[mf][nf], a[mf], b[nf][0], b[nf][1]);
    }
}

__device__ __forceinline__ void load_tiles(uint32_t base, int tid,
                                           const __nv_bfloat16* __restrict__ Ag, int astr,
                                           const __nv_bfloat16* __restrict__ Bg, int bstr) {
#pragma unroll
    for (int i = 0; i < 4; i++) {
        int u = tid + i * 256;
        int r = u >> 3, c = (u & 7) * 8;
        uint32_t off = (uint32_t)(r * (RSE * 2) + c * 2);
        CP16(base + off,          &Ag[(size_t)r * astr + c]);
        CP16(base + TBYTES + off, &Bg[(size_t)r * bstr + c]);
    }
}

// ---------------- kernel 1: KD = keys*S (hi/lo), pack B' --------------------
#define KD_ABYTES 9216
#define KD_STAGE  27648
#define KD_SMEM   (3 * KD_STAGE)

__device__ __forceinline__ void kd_load(uint32_t base, int tid,
                                        const __nv_bfloat16* __restrict__ Ag,
                                        const __nv_bfloat16* __restrict__ Bg) {
#pragma unroll
    for (int i = 0; i < 2; i++) {         // A: 64 rows x 128B
        int u = tid + i * 256;
        int r = u >> 3, c = (u & 7) * 8;
        CP16(base + (uint32_t)(r * (RSE * 2) + c * 2), &Ag[(size_t)r * MM + c]);
    }
#pragma unroll
    for (int i = 0; i < 4; i++) {         // B: 128 rows x 128B
        int u = tid + i * 256;
        int r = u >> 3, c = (u & 7) * 8;
        CP16(base + KD_ABYTES + (uint32_t)(r * (RSE * 2) + c * 2), &Bg[(size_t)r * 512 + c]);
    }
}

__global__ __launch_bounds__(256, 2) void kd_kernel() {
    uint32_t sb = smem_u32(dsm);
    int tid = threadIdx.x, warp = tid >> 5, lane = tid & 31;
    int wm = warp >> 1, wn = warp & 1;
    int n0 = blockIdx.x * 64;

    float acc[8][4];
#pragma unroll
    for (int j = 0; j < 8; j++)
#pragma unroll
        for (int k = 0; k < 4; k++) acc[j][k] = 0.f;

    int lrow  = (lane & 7) + (lane & 8);
    int lcolo = (lane >> 4) << 3;

#define KD_LOAD(st, c) kd_load(sb + (st) * KD_STAGE, tid, \
        &g_Kb[(size_t)n0 * MM + (((c) * 64) & 255)], &g_Sd[(c) * 64])

    KD_LOAD(0, 0); CP_COMMIT();
    KD_LOAD(1, 1); CP_COMMIT();
#pragma unroll 1
    for (int c = 0; c < 8; c++) {
        if (c < 7) asm volatile("cp.async.wait_group 1;" ::: "memory");
        else       asm volatile("cp.async.wait_group 0;" ::: "memory");
        __syncthreads();
        if (c + 2 < 8) { KD_LOAD((c + 2) % 3, c + 2); CP_COMMIT(); }
        uint32_t base = sb + (c % 3) * KD_STAGE;
        uint32_t bbase = base + KD_ABYTES;
#pragma unroll
        for (int kk = 0; kk < 64; kk += 16) {
            uint32_t a[4];
            LDSM4(a, base + (uint32_t)((wm * 16 + lrow) * (RSE * 2) + (kk + lcolo) * 2));
            uint32_t b[8][2];
#pragma unroll
            for (int nq = 0; nq < 4; nq++) {
                uint32_t f[4];
                LDSM4(f, bbase + (uint32_t)((wn * 64 + nq * 16 + lrow) * (RSE * 2)
                                            + (kk + lcolo) * 2));
                b[nq * 2][0] = f[0];     b[nq * 2][1] = f[2];
                b[nq * 2 + 1][0] = f[1]; b[nq * 2 + 1][1] = f[3];
            }
#pragma unroll
            for (int nf = 0; nf < 8; nf++)
                HMMA(acc[nf], a, b[nf][0], b[nf][1]);
        }
    }

    int q = lane & 3, rq = lane >> 2;
#pragma unroll
    for (int nf = 0; nf < 8; nf++) {
        int col = wn * 64 + nf * 8 + q * 2;
#pragma unroll
        for (int h = 0; h < 2; h++) {
            int r = wm * 16 + h * 8 + rq;
            float v0 = acc[nf][h * 2 + 0];
            float v1 = acc[nf][h * 2 + 1];
            __nv_bfloat16 h0 = __float2bfloat16(v0);
            __nv_bfloat16 h1 = __float2bfloat16(v1);
            __nv_bfloat162 hp(h0, h1);
            __nv_bfloat162 lp(__float2bfloat16(v0 - __bfloat162float(h0)),
                              __float2bfloat16(v1 - __bfloat162float(h1)));
            size_t rb = (size_t)(n0 + r) * KMAIN;
            *(__nv_bfloat162*)&g_Bp[rb + col]       = hp;
            *(__nv_bfloat162*)&g_Bp[rb + 128 + col] = hp;
            *(__nv_bfloat162*)&g_Bp[rb + 256 + col] = lp;
        }
    }
}

// ---------------- kernel 2: main GEMM (row-quarter) + partials --------------
__global__ __launch_bounds__(256, 2) void gemm_kernel(float* __restrict__ out, int rb_base) {
    uint32_t sb = smem_u32(dsm);
    int tid = threadIdx.x, warp = tid >> 5, lane = tid & 31;
    int wm = warp >> 1, wn = warp & 1;
    int rb = rb_base + blockIdx.y, cb = blockIdx.x;
    int row0 = rb * 128, col0 = cb * TILE_N;

    __shared__ float sclS[TILE_N];
    __shared__ float redm[128][2];
    __shared__ float reds[128][2];
    if (tid < TILE_N) sclS[tid] = g_scl[col0 + tid];

    float acc[2][8][4];
#pragma unroll
    for (int i = 0; i < 2; i++)
#pragma unroll
        for (int j = 0; j < 8; j++)
#pragma unroll
            for (int k = 0; k < 4; k++) acc[i][j][k] = 0.f;

    int lrow  = (lane & 7) + (lane & 8);
    int lcolo = (lane >> 4) << 3;

#define MG_LOAD(st, c) load_tiles(sb + (st) * STAGE_BYTES, tid, \
        &g_Ap[(size_t)row0 * KMAIN + (c) * 64], KMAIN, \
        &g_Bp[(size_t)col0 * KMAIN + (c) * 64], KMAIN)

    MG_LOAD(0, 0); CP_COMMIT();
    MG_LOAD(1, 1); CP_COMMIT();
#pragma unroll 1
    for (int c = 0; c < 6; c++) {
        if (c < 5) asm volatile("cp.async.wait_group 1;" ::: "memory");
        else       asm volatile("cp.async.wait_group 0;" ::: "memory");
        __syncthreads();
        if (c + 2 < 6) { MG_LOAD((c + 2) % 3, c + 2); CP_COMMIT(); }
        compute_chunk(sb + (c % 3) * STAGE_BYTES, wm, wn, lrow, lcolo, acc);
    }
    __syncthreads();     // all compute done before epilogue aliases buffers

    // ---------------- epilogue ----------------
    float* stage = (float*)dsm;            // [128][132] fp32
    int q = lane & 3, rq = lane >> 2;

    float rmax[2][2];
#pragma unroll
    for (int mf = 0; mf < 2; mf++)
#pragma unroll
        for (int h = 0; h < 2; h++) rmax[mf][h] = -1e30f;

#pragma unroll
    for (int mf = 0; mf < 2; mf++)
#pragma unroll
        for (int nf = 0; nf < 8; nf++) {
            int c = wn * 64 + nf * 8 + q * 2;
            float s0 = sclS[c], s1 = sclS[c + 1];
#pragma unroll
            for (int h = 0; h < 2; h++) {
                float v0 = acc[mf][nf][h * 2 + 0] * s0;
                float v1 = acc[mf][nf][h * 2 + 1] * s1;
                acc[mf][nf][h * 2 + 0] = v0;
                acc[mf][nf][h * 2 + 1] = v1;
                rmax[mf][h] = fmaxf(rmax[mf][h], fmaxf(v0, v1));
                int r = wm * 32 + mf * 16 + h * 8 + rq;
                stage[r * 132 + c]     = v0;
                stage[r * 132 + c + 1] = v1;
            }
        }

#pragma unroll
    for (int mf = 0; mf < 2; mf++)
#pragma unroll
        for (int h = 0; h < 2; h++) {
            float m = rmax[mf][h];
            m = fmaxf(m, __shfl_xor_sync(0xffffffff, m, 1));
            m = fmaxf(m, __shfl_xor_sync(0xffffffff, m, 2));
            if (q == 0) redm[wm * 32 + mf * 16 + h * 8 + rq][wn] = m;
        }
    __syncthreads();

#pragma unroll
    for (int mf = 0; mf < 2; mf++)
#pragma unroll
        for (int h = 0; h < 2; h++) {
            int r = wm * 32 + mf * 16 + h * 8 + rq;
            float m = fmaxf(redm[r][0], redm[r][1]);
            float s = 0.f;
#pragma unroll
            for (int nf = 0; nf < 8; nf++) {
                s += __expf(acc[mf][nf][h * 2 + 0] - m);
                s += __expf(acc[mf][nf][h * 2 + 1] - m);
            }
            s += __shfl_xor_sync(0xffffffff, s, 1);
            s += __shfl_xor_sync(0xffffffff, s, 2);
            if (q == 0) reds[r][wn] = s;
        }
    __syncthreads();

    if (tid < 128) {
        float m = fmaxf(redm[tid][0], redm[tid][1]);
        float s = reds[tid][0] + reds[tid][1];
        g_pmax[(size_t)(row0 + tid) * NCB + cb] = m;
        g_psum[(size_t)(row0 + tid) * NCB + cb] = s;
    }

#pragma unroll
    for (int rr = 0; rr < 4; rr++) {
        int r = rr * 32 + warp * 4 + (lane >> 3);
#pragma unroll
        for (int k = 0; k < 4; k++) {
            int col = (lane & 7) * 4 + k * 32;
            float4 v = *(const float4*)&stage[r * 132 + col];
            *(float4*)&out[(size_t)(row0 + r) * NK + col0 + col] = v;
        }
    }
}

// ---------------- kernel 3: merge partials (4 rows per block, float4) -------
__global__ __launch_bounds__(256) void reduce_kernel(int row_base) {
    int t = threadIdx.x;
    int sub = t >> 6, l = t & 63;
    int lane = t & 31, w = (t >> 5) & 1;
    int b = row_base + blockIdx.x * 4 + sub;
    __shared__ float sm[4][2], ss[4][2];
    float4 pm = ((const float4*)&g_pmax[(size_t)b * NCB])[l];
    float4 ps = ((const float4*)&g_psum[(size_t)b * NCB])[l];
    float M = fmaxf(fmaxf(pm.x, pm.y), fmaxf(pm.z, pm.w));
#pragma unroll
    for (int o = 16; o; o >>= 1) M = fmaxf(M, __shfl_xor_sync(0xffffffff, M, o));
    if (lane == 0) sm[sub][w] = M;
    __syncthreads();
    M = fmaxf(sm[sub][0], sm[sub][1]);
    float s = ps.x * __expf(pm.x - M) + ps.y * __expf(pm.y - M)
            + ps.z * __expf(pm.z - M) + ps.w * __expf(pm.w - M);
#pragma unroll
    for (int o = 16; o; o >>= 1) s += __shfl_xor_sync(0xffffffff, s, o);
    if (lane == 0) ss[sub][w] = s;
    __syncthreads();
    if (l == 0) {
        g_rowm[b] = M;
        g_rowinv[b] = 1.f / (ss[sub][0] + ss[sub][1]);
    }
}

// ---------------- kernel 4: finalize quarter, 4x ILP per thread -------------
__global__ __launch_bounds__(256) void finalize_kernel(float* __restrict__ out, int row_base) {
    int b = row_base + (int)(blockIdx.x >> 3);
    size_t seg = (size_t)b * 8192 + (size_t)(blockIdx.x & 7) * 1024;   // float4 units
    float m = g_rowm[b], inv = g_rowinv[b];
    float4* o4 = (float4*)out;
    float4 v[4];
#pragma unroll
    for (int k = 0; k < 4; k++) v[k] = o4[seg + threadIdx.x + k * 256];
#pragma unroll
    for (int k = 0; k < 4; k++) {
        v[k].x = __expf(v[k].x - m) * inv;
        v[k].y = __expf(v[k].y - m) * inv;
        v[k].z = __expf(v[k].z - m) * inv;
        v[k].w = __expf(v[k].w - m) * inv;
    }
#pragma unroll
    for (int k = 0; k < 4; k++) o4[seg + threadIdx.x + k * 256] = v[k];
}

// ---------------- launcher: graph-parallel branches -------------------------
extern "C" void kernel_launch(void* const* d_in, const int* in_sizes, int n_in,
                              void* d_out, int out_size) {
    const float* query  = (const float*)d_in[0];
    const float* keys   = (const float*)d_in[1];
    const float* norms  = (const float*)d_in[2];
    const float* sketch = (const float*)d_in[3];
    float* out = (float*)d_out;

    // lazy one-time resource init (no device memory; identical work every call)
    static cudaStream_t s1 = nullptr;
    static cudaEvent_t evFork, evPA, evQ[NQUART], evJoin;
    if (!s1) {
        cudaStreamCreateWithFlags(&s1, cudaStreamNonBlocking);
        cudaEventCreateWithFlags(&evFork, cudaEventDisableTiming);
        cudaEventCreateWithFlags(&evPA,   cudaEventDisableTiming);
        for (int i = 0; i < NQUART; i++)
            cudaEventCreateWithFlags(&evQ[i], cudaEventDisableTiming);
        cudaEventCreateWithFlags(&evJoin, cudaEventDisableTiming);
        cudaFuncSetAttribute(kd_kernel,   cudaFuncAttributeMaxDynamicSharedMemorySize, KD_SMEM);
        cudaFuncSetAttribute(gemm_kernel, cudaFuncAttributeMaxDynamicSharedMemorySize, SMEM_BYTES);
    }

    // fork side stream from the (possibly capturing) main stream
    cudaEventRecord(evFork, 0);
    cudaStreamWaitEvent(s1, evFork, 0);

    // side branch: prep_A (independent of keys path)
    prep_A_kernel<<<BQ * DD / 256, 256, 0, s1>>>(query);
    cudaEventRecord(evPA, s1);

    // main branch: keys -> bf16, S prep, KD GEMM
    convert_keys_kernel<<<NK * MM / 1024, 256>>>(keys, norms);
    prep_S_kernel<<<MM * DD / 256, 256>>>(sketch);
    kd_kernel<<<NK / 64, 256, KD_SMEM>>>();
    cudaStreamWaitEvent(0, evPA, 0);

    // quartered GEMM on main stream; finalize chain on side stream
    for (int qi = 0; qi < NQUART; qi++) {
        dim3 g(NCB, RB_PER_Q);
        gemm_kernel<<<g, 256, SMEM_BYTES>>>(out, qi * RB_PER_Q);
        cudaEventRecord(evQ[qi], 0);
    }
    for (int qi = 0; qi < NQUART; qi++) {
        int row_base = qi * RB_PER_Q * 128;     // 512 rows per quarter
        cudaStreamWaitEvent(s1, evQ[qi], 0);
        reduce_kernel<<<(BQ / NQUART) / 4, 256, 0, s1>>>(row_base);
        finalize_kernel<<<(BQ / NQUART) * 8, 256, 0, s1>>>(out, row_base);
    }
    cudaEventRecord(evJoin, s1);
    cudaStreamWaitEvent(0, evJoin, 0);
}

// round 13
// speedup vs baseline: 1.4591x; 1.0003x over previous
#include <cuda_runtime.h>
#include <cuda_bf16.h>
#include <cstdint>

#define BQ   2048
#define DD   128
#define MM   256
#define NK   32768
#define EST_CONST 0.0048957583f   // sqrt(pi/2)/256

#define TILE_N 128
#define NCB    (NK / TILE_N)      // 256 column blocks
#define KMAIN  384                // [Qhi|Qlo|Qhi] x [KDhi|KDhi|KDlo]
#define NRB    (BQ / 128)         // 16 row blocks
#define NHALF  2
#define RB_PER_H (NRB / NHALF)    // 8 row blocks per half (1024 rows)

// ---------------- device scratch ----------------
__device__ __align__(16) __nv_bfloat16 g_Kb[NK * MM];      // keys bf16 exact
__device__ __align__(16) __nv_bfloat16 g_Sd[DD * 512];     // S^T hi|lo  [d][512]
__device__ __align__(16) __nv_bfloat16 g_Ap[BQ * KMAIN];   // [Qhi|Qlo|Qhi]
__device__ __align__(16) __nv_bfloat16 g_Bp[NK * KMAIN];   // [KDhi|KDhi|KDlo]
__device__ float g_scl[NK];
__device__ float g_pmax[BQ * NCB];
__device__ float g_psum[BQ * NCB];
__device__ float g_rowm[BQ];
__device__ float g_rowinv[BQ];

__device__ __forceinline__ uint32_t smem_u32(const void* p) {
    uint32_t a;
    asm("{ .reg .u64 t; cvta.to.shared.u64 t, %1; cvt.u32.u64 %0, t; }" : "=r"(a) : "l"(p));
    return a;
}
#define CP16(dst, src) asm volatile("cp.async.cg.shared.global [%0], [%1], 16;" :: "r"(dst), "l"(src))
#define CP_COMMIT()    asm volatile("cp.async.commit_group;" ::: "memory")

// ---------------- kernel 0: keys -> bf16 (exact), scales --------------------
__global__ __launch_bounds__(256) void convert_keys_kernel(const float* __restrict__ keys,
                                                           const float* __restrict__ norms) {
    int i = blockIdx.x * blockDim.x + threadIdx.x;   // over float4
    float4 v = ((const float4*)keys)[i];
    __nv_bfloat162* o = (__nv_bfloat162*)g_Kb;
    o[i * 2]     = __nv_bfloat162(__float2bfloat16(v.x), __float2bfloat16(v.y));
    o[i * 2 + 1] = __nv_bfloat162(__float2bfloat16(v.z), __float2bfloat16(v.w));
    if (i < NK) g_scl[i] = EST_CONST * norms[i];
}

// ---------------- kernel 0b: S -> transposed hi/lo --------------------------
__global__ __launch_bounds__(256) void prep_S_kernel(const float* __restrict__ S) {
    int idx = blockIdx.x * blockDim.x + threadIdx.x;   // 32768 elems
    int m = idx >> 7, d = idx & 127;
    float v = S[m * DD + d];
    __nv_bfloat16 hi = __float2bfloat16(v);
    float lo = v - __bfloat162float(hi);
    g_Sd[d * 512 + m]       = hi;
    g_Sd[d * 512 + 256 + m] = __float2bfloat16(lo);
}

// ---------------- kernel 0c: Q -> [Qhi|Qlo|Qhi] -----------------------------
__global__ __launch_bounds__(256) void prep_A_kernel(const float* __restrict__ q) {
    int idx = blockIdx.x * blockDim.x + threadIdx.x;   // 2048*128
    int b = idx >> 7, d = idx & 127;
    float v = q[idx];
    __nv_bfloat16 hi = __float2bfloat16(v);
    float lo = v - __bfloat162float(hi);
    g_Ap[b * KMAIN + d]       = hi;
    g_Ap[b * KMAIN + 128 + d] = __float2bfloat16(lo);
    g_Ap[b * KMAIN + 256 + d] = hi;
}

// ---------------- shared GEMM machinery ----------------
#define RSE 72                          // smem row elems (144 B)
#define TBYTES (128 * RSE * 2)          // 18432 per operand tile
#define STAGE_BYTES (2 * TBYTES)        // 36864
#define SMEM_BYTES  (3 * STAGE_BYTES)   // 110592

extern __shared__ char dsm[];

#define HMMA(acc, a, b0, b1) \
    asm volatile("mma.sync.aligned.m16n8k16.row.col.f32.bf16.bf16.f32 " \
                 "{%0,%1,%2,%3}, {%4,%5,%6,%7}, {%8,%9}, {%0,%1,%2,%3};" \
                 : "+f"((acc)[0]), "+f"((acc)[1]), "+f"((acc)[2]), "+f"((acc)[3]) \
                 : "r"((a)[0]), "r"((a)[1]), "r"((a)[2]), "r"((a)[3]), "r"(b0), "r"(b1))

#define LDSM4(f, addr) \
    asm volatile("ldmatrix.sync.aligned.m8n8.x4.shared.b16 {%0,%1,%2,%3}, [%4];" \
                 : "=r"((f)[0]), "=r"((f)[1]), "=r"((f)[2]), "=r"((f)[3]) : "r"(addr))

__device__ __forceinline__ void compute_chunk(uint32_t base, int wm, int wn,
                                              int lrow, int lcolo, float acc[2][8][4]) {
    uint32_t bbase = base + TBYTES;
#pragma unroll
    for (int kk = 0; kk < 64; kk += 16) {
        uint32_t a[2][4];
#pragma unroll
        for (int mf = 0; mf < 2; mf++)
            LDSM4(a[mf], base + (uint32_t)((wm * 32 + mf * 16 + lrow) * (RSE * 2)
                                           + (kk + lcolo) * 2));
        uint32_t b[8][2];
#pragma unroll
        for (int nq = 0; nq < 4; nq++) {
            uint32_t f[4];
            LDSM4(f, bbase + (uint32_t)((wn * 64 + nq * 16 + lrow) * (RSE * 2)
                                        + (kk + lcolo) * 2));
            b[nq * 2][0] = f[0];     b[nq * 2][1] = f[2];
            b[nq * 2 + 1][0] = f[1]; b[nq * 2 + 1][1] = f[3];
        }
#pragma unroll
        for (int mf = 0; mf < 2; mf++)
#pragma unroll
            for (int nf = 0; nf < 8; nf++)
                HMMA(acc[mf][nf], a[mf], b[nf][0], b[nf][1]);
    }
}

__device__ __forceinline__ void load_tiles(uint32_t base, int tid,
                                           const __nv_bfloat16* __restrict__ Ag, int astr,
                                           const __nv_bfloat16* __restrict__ Bg, int bstr) {
#pragma unroll
    for (int i = 0; i < 4; i++) {
        int u = tid + i * 256;
        int r = u >> 3, c = (u & 7) * 8;
        uint32_t off = (uint32_t)(r * (RSE * 2) + c * 2);
        CP16(base + off,          &Ag[(size_t)r * astr + c]);
        CP16(base + TBYTES + off, &Bg[(size_t)r * bstr + c]);
    }
}

// ---------------- kernel 1: KD = keys*S (hi/lo), pack B' --------------------
#define KD_ABYTES 9216
#define KD_STAGE  27648
#define KD_SMEM   (3 * KD_STAGE)

__device__ __forceinline__ void kd_load(uint32_t base, int tid,
                                        const __nv_bfloat16* __restrict__ Ag,
                                        const __nv_bfloat16* __restrict__ Bg) {
#pragma unroll
    for (int i = 0; i < 2; i++) {         // A: 64 rows x 128B
        int u = tid + i * 256;
        int r = u >> 3, c = (u & 7) * 8;
        CP16(base + (uint32_t)(r * (RSE * 2) + c * 2), &Ag[(size_t)r * MM + c]);
    }
#pragma unroll
    for (int i = 0; i < 4; i++) {         // B: 128 rows x 128B
        int u = tid + i * 256;
        int r = u >> 3, c = (u & 7) * 8;
        CP16(base + KD_ABYTES + (uint32_t)(r * (RSE * 2) + c * 2), &Bg[(size_t)r * 512 + c]);
    }
}

__global__ __launch_bounds__(256, 2) void kd_kernel() {
    uint32_t sb = smem_u32(dsm);
    int tid = threadIdx.x, warp = tid >> 5, lane = tid & 31;
    int wm = warp >> 1, wn = warp & 1;
    int n0 = blockIdx.x * 64;

    float acc[8][4];
#pragma unroll
    for (int j = 0; j < 8; j++)
#pragma unroll
        for (int k = 0; k < 4; k++) acc[j][k] = 0.f;

    int lrow  = (lane & 7) + (lane & 8);
    int lcolo = (lane >> 4) << 3;

#define KD_LOAD(st, c) kd_load(sb + (st) * KD_STAGE, tid, \
        &g_Kb[(size_t)n0 * MM + (((c) * 64) & 255)], &g_Sd[(c) * 64])

    KD_LOAD(0, 0); CP_COMMIT();
    KD_LOAD(1, 1); CP_COMMIT();
#pragma unroll 1
    for (int c = 0; c < 8; c++) {
        if (c < 7) asm volatile("cp.async.wait_group 1;" ::: "memory");
        else       asm volatile("cp.async.wait_group 0;" ::: "memory");
        __syncthreads();
        if (c + 2 < 8) { KD_LOAD((c + 2) % 3, c + 2); CP_COMMIT(); }
        uint32_t base = sb + (c % 3) * KD_STAGE;
        uint32_t bbase = base + KD_ABYTES;
#pragma unroll
        for (int kk = 0; kk < 64; kk += 16) {
            uint32_t a[4];
            LDSM4(a, base + (uint32_t)((wm * 16 + lrow) * (RSE * 2) + (kk + lcolo) * 2));
            uint32_t b[8][2];
#pragma unroll
            for (int nq = 0; nq < 4; nq++) {
                uint32_t f[4];
                LDSM4(f, bbase + (uint32_t)((wn * 64 + nq * 16 + lrow) * (RSE * 2)
                                            + (kk + lcolo) * 2));
                b[nq * 2][0] = f[0];     b[nq * 2][1] = f[2];
                b[nq * 2 + 1][0] = f[1]; b[nq * 2 + 1][1] = f[3];
            }
#pragma unroll
            for (int nf = 0; nf < 8; nf++)
                HMMA(acc[nf], a, b[nf][0], b[nf][1]);
        }
    }

    int q = lane & 3, rq = lane >> 2;
#pragma unroll
    for (int nf = 0; nf < 8; nf++) {
        int col = wn * 64 + nf * 8 + q * 2;
#pragma unroll
        for (int h = 0; h < 2; h++) {
            int r = wm * 16 + h * 8 + rq;
            float v0 = acc[nf][h * 2 + 0];
            float v1 = acc[nf][h * 2 + 1];
            __nv_bfloat16 h0 = __float2bfloat16(v0);
            __nv_bfloat16 h1 = __float2bfloat16(v1);
            __nv_bfloat162 hp(h0, h1);
            __nv_bfloat162 lp(__float2bfloat16(v0 - __bfloat162float(h0)),
                              __float2bfloat16(v1 - __bfloat162float(h1)));
            size_t rb = (size_t)(n0 + r) * KMAIN;
            *(__nv_bfloat162*)&g_Bp[rb + col]       = hp;
            *(__nv_bfloat162*)&g_Bp[rb + 128 + col] = hp;
            *(__nv_bfloat162*)&g_Bp[rb + 256 + col] = lp;
        }
    }
}

// ---------------- kernel 2: main GEMM (row-half) + partials -----------------
__global__ __launch_bounds__(256, 2) void gemm_kernel(float* __restrict__ out, int rb_base) {
    uint32_t sb = smem_u32(dsm);
    int tid = threadIdx.x, warp = tid >> 5, lane = tid & 31;
    int wm = warp >> 1, wn = warp & 1;
    int rb = rb_base + blockIdx.y, cb = blockIdx.x;
    int row0 = rb * 128, col0 = cb * TILE_N;

    __shared__ float sclS[TILE_N];
    __shared__ float redm[128][2];
    __shared__ float reds[128][2];
    if (tid < TILE_N) sclS[tid] = g_scl[col0 + tid];

    float acc[2][8][4];
#pragma unroll
    for (int i = 0; i < 2; i++)
#pragma unroll
        for (int j = 0; j < 8; j++)
#pragma unroll
            for (int k = 0; k < 4; k++) acc[i][j][k] = 0.f;

    int lrow  = (lane & 7) + (lane & 8);
    int lcolo = (lane >> 4) << 3;

#define MG_LOAD(st, c) load_tiles(sb + (st) * STAGE_BYTES, tid, \
        &g_Ap[(size_t)row0 * KMAIN + (c) * 64], KMAIN, \
        &g_Bp[(size_t)col0 * KMAIN + (c) * 64], KMAIN)

    MG_LOAD(0, 0); CP_COMMIT();
    MG_LOAD(1, 1); CP_COMMIT();
#pragma unroll 1
    for (int c = 0; c < 6; c++) {
        if (c < 5) asm volatile("cp.async.wait_group 1;" ::: "memory");
        else       asm volatile("cp.async.wait_group 0;" ::: "memory");
        __syncthreads();
        if (c + 2 < 6) { MG_LOAD((c + 2) % 3, c + 2); CP_COMMIT(); }
        compute_chunk(sb + (c % 3) * STAGE_BYTES, wm, wn, lrow, lcolo, acc);
    }
    __syncthreads();     // all compute done before epilogue aliases buffers

    // ---------------- epilogue ----------------
    float* stage = (float*)dsm;            // [128][132] fp32
    int q = lane & 3, rq = lane >> 2;

    float rmax[2][2];
#pragma unroll
    for (int mf = 0; mf < 2; mf++)
#pragma unroll
        for (int h = 0; h < 2; h++) rmax[mf][h] = -1e30f;

#pragma unroll
    for (int mf = 0; mf < 2; mf++)
#pragma unroll
        for (int nf = 0; nf < 8; nf++) {
            int c = wn * 64 + nf * 8 + q * 2;
            float s0 = sclS[c], s1 = sclS[c + 1];
#pragma unroll
            for (int h = 0; h < 2; h++) {
                float v0 = acc[mf][nf][h * 2 + 0] * s0;
                float v1 = acc[mf][nf][h * 2 + 1] * s1;
                acc[mf][nf][h * 2 + 0] = v0;
                acc[mf][nf][h * 2 + 1] = v1;
                rmax[mf][h] = fmaxf(rmax[mf][h], fmaxf(v0, v1));
                int r = wm * 32 + mf * 16 + h * 8 + rq;
                stage[r * 132 + c]     = v0;
                stage[r * 132 + c + 1] = v1;
            }
        }

#pragma unroll
    for (int mf = 0; mf < 2; mf++)
#pragma unroll
        for (int h = 0; h < 2; h++) {
            float m = rmax[mf][h];
            m = fmaxf(m, __shfl_xor_sync(0xffffffff, m, 1));
            m = fmaxf(m, __shfl_xor_sync(0xffffffff, m, 2));
            if (q == 0) redm[wm * 32 + mf * 16 + h * 8 + rq][wn] = m;
        }
    __syncthreads();

#pragma unroll
    for (int mf = 0; mf < 2; mf++)
#pragma unroll
        for (int h = 0; h < 2; h++) {
            int r = wm * 32 + mf * 16 + h * 8 + rq;
            float m = fmaxf(redm[r][0], redm[r][1]);
            float s = 0.f;
#pragma unroll
            for (int nf = 0; nf < 8; nf++) {
                s += __expf(acc[mf][nf][h * 2 + 0] - m);
                s += __expf(acc[mf][nf][h * 2 + 1] - m);
            }
            s += __shfl_xor_sync(0xffffffff, s, 1);
            s += __shfl_xor_sync(0xffffffff, s, 2);
            if (q == 0) reds[r][wn] = s;
        }
    __syncthreads();

    if (tid < 128) {
        float m = fmaxf(redm[tid][0], redm[tid][1]);
        float s = reds[tid][0] + reds[tid][1];
        g_pmax[(size_t)(row0 + tid) * NCB + cb] = m;
        g_psum[(size_t)(row0 + tid) * NCB + cb] = s;
    }

#pragma unroll
    for (int rr = 0; rr < 4; rr++) {
        int r = rr * 32 + warp * 4 + (lane >> 3);
#pragma unroll
        for (int k = 0; k < 4; k++) {
            int col = (lane & 7) * 4 + k * 32;
            float4 v = *(const float4*)&stage[r * 132 + col];
            *(float4*)&out[(size_t)(row0 + r) * NK + col0 + col] = v;
        }
    }
}

// ---------------- kernel 3: merge partials (4 rows per block, float4) -------
__global__ __launch_bounds__(256) void reduce_kernel(int row_base) {
    int t = threadIdx.x;
    int sub = t >> 6, l = t & 63;
    int lane = t & 31, w = (t >> 5) & 1;
    int b = row_base + blockIdx.x * 4 + sub;
    __shared__ float sm[4][2], ss[4][2];
    float4 pm = ((const float4*)&g_pmax[(size_t)b * NCB])[l];
    float4 ps = ((const float4*)&g_psum[(size_t)b * NCB])[l];
    float M = fmaxf(fmaxf(pm.x, pm.y), fmaxf(pm.z, pm.w));
#pragma unroll
    for (int o = 16; o; o >>= 1) M = fmaxf(M, __shfl_xor_sync(0xffffffff, M, o));
    if (lane == 0) sm[sub][w] = M;
    __syncthreads();
    M = fmaxf(sm[sub][0], sm[sub][1]);
    float s = ps.x * __expf(pm.x - M) + ps.y * __expf(pm.y - M)
            + ps.z * __expf(pm.z - M) + ps.w * __expf(pm.w - M);
#pragma unroll
    for (int o = 16; o; o >>= 1) s += __shfl_xor_sync(0xffffffff, s, o);
    if (lane == 0) ss[sub][w] = s;
    __syncthreads();
    if (l == 0) {
        g_rowm[b] = M;
        g_rowinv[b] = 1.f / (ss[sub][0] + ss[sub][1]);
    }
}

// ---------------- kernel 4: finalize half, 4x ILP per thread ----------------
__global__ __launch_bounds__(256) void finalize_kernel(float* __restrict__ out, int row_base) {
    int b = row_base + (int)(blockIdx.x >> 3);
    size_t seg = (size_t)b * 8192 + (size_t)(blockIdx.x & 7) * 1024;   // float4 units
    float m = g_rowm[b], inv = g_rowinv[b];
    float4* o4 = (float4*)out;
    float4 v[4];
#pragma unroll
    for (int k = 0; k < 4; k++) v[k] = o4[seg + threadIdx.x + k * 256];
#pragma unroll
    for (int k = 0; k < 4; k++) {
        v[k].x = __expf(v[k].x - m) * inv;
        v[k].y = __expf(v[k].y - m) * inv;
        v[k].z = __expf(v[k].z - m) * inv;
        v[k].w = __expf(v[k].w - m) * inv;
    }
#pragma unroll
    for (int k = 0; k < 4; k++) o4[seg + threadIdx.x + k * 256] = v[k];
}

// ---------------- launcher: graph-parallel branches, 2-way split ------------
extern "C" void kernel_launch(void* const* d_in, const int* in_sizes, int n_in,
                              void* d_out, int out_size) {
    const float* query  = (const float*)d_in[0];
    const float* keys   = (const float*)d_in[1];
    const float* norms  = (const float*)d_in[2];
    const float* sketch = (const float*)d_in[3];
    float* out = (float*)d_out;

    // lazy one-time resource init (no device memory; identical work every call)
    static cudaStream_t s1 = nullptr;
    static cudaEvent_t evFork, evPA, evQ[NHALF], evJoin;
    if (!s1) {
        cudaStreamCreateWithFlags(&s1, cudaStreamNonBlocking);
        cudaEventCreateWithFlags(&evFork, cudaEventDisableTiming);
        cudaEventCreateWithFlags(&evPA,   cudaEventDisableTiming);
        for (int i = 0; i < NHALF; i++)
            cudaEventCreateWithFlags(&evQ[i], cudaEventDisableTiming);
        cudaEventCreateWithFlags(&evJoin, cudaEventDisableTiming);
        cudaFuncSetAttribute(kd_kernel,   cudaFuncAttributeMaxDynamicSharedMemorySize, KD_SMEM);
        cudaFuncSetAttribute(gemm_kernel, cudaFuncAttributeMaxDynamicSharedMemorySize, SMEM_BYTES);
    }

    // fork side stream from the (possibly capturing) main stream
    cudaEventRecord(evFork, 0);
    cudaStreamWaitEvent(s1, evFork, 0);

    // side branch: prep_A (independent of keys path)
    prep_A_kernel<<<BQ * DD / 256, 256, 0, s1>>>(query);
    cudaEventRecord(evPA, s1);

    // main branch: keys -> bf16, S prep, KD GEMM
    convert_keys_kernel<<<NK * MM / 1024, 256>>>(keys, norms);
    prep_S_kernel<<<MM * DD / 256, 256>>>(sketch);
    kd_kernel<<<NK / 64, 256, KD_SMEM>>>();
    cudaStreamWaitEvent(0, evPA, 0);

    // halved GEMM on main stream; reduce+finalize chained on side stream
    for (int qi = 0; qi < NHALF; qi++) {
        dim3 g(NCB, RB_PER_H);
        gemm_kernel<<<g, 256, SMEM_BYTES>>>(out, qi * RB_PER_H);
        cudaEventRecord(evQ[qi], 0);
    }
    for (int qi = 0; qi < NHALF; qi++) {
        int row_base = qi * RB_PER_H * 128;     // 1024 rows per half
        cudaStreamWaitEvent(s1, evQ[qi], 0);
        reduce_kernel<<<(BQ / NHALF) / 4, 256, 0, s1>>>(row_base);
        finalize_kernel<<<(BQ / NHALF) * 8, 256, 0, s1>>>(out, row_base);
    }
    cudaEventRecord(evJoin, s1);
    cudaStreamWaitEvent(0, evJoin, 0);
}